// round 14
// baseline (speedup 1.0000x reference)
#include <cuda_runtime.h>
#include <cuda_fp16.h>
#include <cstdint>

#define NN   4096
#define FF   256
#define KH   8
#define FPD  64
#define KFP  512   // K*FP
#define LOG2E 1.4426950408889634f

// ---------------- scratch (static device globals; no allocation) -------------
__device__ float g_hl[KH * NN];                   // hl[k][n] * log2(e)
__device__ uint2 g_hrB[KH * NN / 2];              // packed { fp16x2(B,B'), fp16x2(B2,B2') }
__device__ unsigned short g_maskh[NN * NN];       // 32 MB fp16 mask (1.0 / 0.0)
__device__ unsigned short g_xeT_h[KH * FPD * NN]; // 4 MB: fp16(xe)[k][f][n]

// =================== helpers (baseline PTX only) ============================
__device__ __forceinline__ uint32_t smem_u32(const void* p) {
    uint32_t a;
    asm("{ .reg .u64 t; cvta.to.shared.u64 t, %1; cvt.u32.u64 %0, t; }" : "=r"(a) : "l"(p));
    return a;
}
__device__ __forceinline__ uint32_t h16x2(float x, float y) {
    uint32_t r;
    asm("cvt.rn.f16x2.f32 %0, %1, %2;" : "=r"(r) : "f"(y), "f"(x));
    return r;
}
__device__ __forceinline__ float ex2f(float x) {
    float r;
    asm("ex2.approx.ftz.f32 %0, %1;" : "=f"(r) : "f"(x));
    return r;
}
__device__ __forceinline__ uint32_t hmul2(uint32_t a, uint32_t b) {
    uint32_t r;
    asm("mul.f16x2 %0, %1, %2;" : "=r"(r) : "r"(a), "r"(b));
    return r;
}
__device__ __forceinline__ uint32_t hmax2(uint32_t a, uint32_t b) {
    uint32_t r;
    asm("max.f16x2 %0, %1, %2;" : "=r"(r) : "r"(a), "r"(b));
    return r;
}
__device__ __forceinline__ uint32_t lds32(uint32_t a) {
    uint32_t r;
    asm volatile("ld.shared.b32 %0, [%1];" : "=r"(r) : "r"(a));
    return r;
}
#define LDSM4(R0, R1, R2, R3, A) \
    asm volatile("ldmatrix.sync.aligned.m8n8.x4.shared.b16 {%0,%1,%2,%3}, [%4];" \
                 : "=r"(R0), "=r"(R1), "=r"(R2), "=r"(R3) : "r"(A))
#define MMAH(D, A0, A1, A2, A3, B0, B1) \
    asm volatile("mma.sync.aligned.m16n8k16.row.col.f32.f16.f16.f32 " \
                 "{%0,%1,%2,%3}, {%4,%5,%6,%7}, {%8,%9}, {%0,%1,%2,%3};" \
                 : "+f"((D)[0]), "+f"((D)[1]), "+f"((D)[2]), "+f"((D)[3]) \
                 : "r"(A0), "r"(A1), "r"(A2), "r"(A3), "r"(B0), "r"(B1))
#define CP16(dst, src) \
    asm volatile("cp.async.cg.shared.global [%0], [%1], 16;" :: "r"(dst), "l"(src) : "memory")
#define CP_COMMIT() asm volatile("cp.async.commit_group;" ::: "memory")
#define CP_WAIT(n)  asm volatile("cp.async.wait_group %0;" :: "n"(n) : "memory")

// ---------------- Fused kernel: GEMM(+hl/hrB+fp16 transpose) || mask canon ---
// Blocks [0,256): xe GEMM per (row-block, head). Blocks [256, 256+2048):
// mask canon to fp16 0/1 (32 elems/thread). Format detection is per-canon-
// block: 64 uniform head words; words-format <=> all in {0,1,0x3F800000}
// (uint8 packing collides with prob 2^-3/word -> 2^-192 for 64 words).
#define CANON_BLKS 2048   // 2048 * 256 thr * 32 elems = 16M = NN*NN

__global__ void __launch_bounds__(256) fused_gemm_canon(
        const float* __restrict__ x, const float* __restrict__ W,
        const float* __restrict__ b, const float* __restrict__ al,
        const float* __restrict__ ar, const void* __restrict__ m) {
    if (blockIdx.x >= 256) {
        // ---- per-block format detection (uniform loads, L1/L2 broadcast) ----
        bool words = true;
        const unsigned int* mw = (const unsigned int*)m;
#pragma unroll 16
        for (int i = 0; i < 64; i++) {
            unsigned int w = mw[i];
            if (w > 1u && w != 0x3F800000u) words = false;
        }
        // ---- canon: 32 elements per thread -> fp16 0/1 ----
        int idx = (blockIdx.x - 256) * 256 + threadIdx.x;   // 0..524287
        int e0 = idx * 32;
        int n  = e0 >> 12;
        int m0 = e0 & 4095;
        uint32_t h[16];
        if (words) {               // 4-byte words (int32 or float32): nonzero test
            const uint4* p = (const uint4*)((const unsigned int*)m + (size_t)n * NN + m0);
#pragma unroll
            for (int i = 0; i < 8; i++) {
                uint4 w = p[i];
                h[2 * i]     = (w.x ? 0x3C00u : 0u) | (w.y ? 0x3C000000u : 0u);
                h[2 * i + 1] = (w.z ? 0x3C00u : 0u) | (w.w ? 0x3C000000u : 0u);
            }
        } else {                   // packed uint8
            const uint4* p = (const uint4*)((const unsigned char*)m + (size_t)n * NN + m0);
            uint4 w01 = p[0], w23 = p[1];
            unsigned wv[8] = {w01.x, w01.y, w01.z, w01.w, w23.x, w23.y, w23.z, w23.w};
#pragma unroll
            for (int i = 0; i < 8; i++) {
                unsigned wq = wv[i];
                h[2 * i]     = ((wq & 0x000000FFu) ? 0x3C00u : 0u) | ((wq & 0x0000FF00u) ? 0x3C000000u : 0u);
                h[2 * i + 1] = ((wq & 0x00FF0000u) ? 0x3C00u : 0u) | ((wq & 0xFF000000u) ? 0x3C000000u : 0u);
            }
        }
        uint4* hdst = (uint4*)(g_maskh + (size_t)n * NN + m0);
#pragma unroll
        for (int i = 0; i < 4; i++)
            hdst[i] = make_uint4(h[4 * i], h[4 * i + 1], h[4 * i + 2], h[4 * i + 3]);
        return;
    }

    // ===================== xe GEMM (blocks 0..255) ==========================
    __shared__ float a_s[16][128];
    __shared__ float b_s[16][64];
    const int gb  = blockIdx.x;
    const int tid = threadIdx.x;
    const int tx = tid & 15;
    const int ty = tid >> 4;
    const int row0 = (gb >> 3) * 128;
    const int k    = gb & 7;              // head
    const int col0 = k * 64;

    float acc[8][4];
#pragma unroll
    for (int i = 0; i < 8; i++)
#pragma unroll
        for (int j = 0; j < 4; j++) acc[i][j] = 0.0f;

    for (int k0 = 0; k0 < FF; k0 += 16) {
#pragma unroll
        for (int u = 0; u < 2; u++) {
            int f4 = tid * 2 + u;
            int r  = f4 >> 2;
            int c4 = f4 & 3;
            float4 v = *(const float4*)&x[(size_t)(row0 + r) * FF + k0 + c4 * 4];
            a_s[c4 * 4 + 0][r] = v.x; a_s[c4 * 4 + 1][r] = v.y;
            a_s[c4 * 4 + 2][r] = v.z; a_s[c4 * 4 + 3][r] = v.w;
        }
        {
            int o  = tid >> 2;
            int c4 = tid & 3;
            float4 v = *(const float4*)&W[(size_t)(col0 + o) * FF + k0 + c4 * 4];
            b_s[c4 * 4 + 0][o] = v.x; b_s[c4 * 4 + 1][o] = v.y;
            b_s[c4 * 4 + 2][o] = v.z; b_s[c4 * 4 + 3][o] = v.w;
        }
        __syncthreads();
#pragma unroll
        for (int kk = 0; kk < 16; kk++) {
            float a_f[8], b_f[4];
#pragma unroll
            for (int i = 0; i < 8; i++) a_f[i] = a_s[kk][ty * 8 + i];
#pragma unroll
            for (int j = 0; j < 4; j++) b_f[j] = b_s[kk][tx * 4 + j];
#pragma unroll
            for (int i = 0; i < 8; i++)
#pragma unroll
                for (int j = 0; j < 4; j++) acc[i][j] += a_f[i] * b_f[j];
        }
        __syncthreads();
    }
    float4 bias = *(const float4*)&b[col0 + tx * 4];
#pragma unroll
    for (int i = 0; i < 8; i++) {
        acc[i][0] += bias.x; acc[i][1] += bias.y;
        acc[i][2] += bias.z; acc[i][3] += bias.w;
    }
    // ---- fused hl/hr: partial dots, butterfly over tx ----
    float4 al4 = *(const float4*)&al[k * FPD + tx * 4];
    float4 ar4 = *(const float4*)&ar[k * FPD + tx * 4];
    float lsum[8], rsum[8];
#pragma unroll
    for (int i = 0; i < 8; i++) {
        float l = acc[i][0] * al4.x + acc[i][1] * al4.y + acc[i][2] * al4.z + acc[i][3] * al4.w;
        float r = acc[i][0] * ar4.x + acc[i][1] * ar4.y + acc[i][2] * ar4.z + acc[i][3] * ar4.w;
#pragma unroll
        for (int off = 8; off; off >>= 1) {
            l += __shfl_xor_sync(0xFFFFFFFFu, l, off);
            r += __shfl_xor_sync(0xFFFFFFFFu, r, off);
        }
        lsum[i] = l; rsum[i] = r;
    }
    if (tx == 0) {
#pragma unroll
        for (int i = 0; i < 8; i++)
            g_hl[k * NN + row0 + ty * 8 + i] = lsum[i] * LOG2E;
#pragma unroll
        for (int i2 = 0; i2 < 4; i2++) {
            float ra = rsum[2 * i2] * LOG2E, rb = rsum[2 * i2 + 1] * LOG2E;
            uint32_t bx = h16x2(ex2f(ra), ex2f(rb));
            uint32_t by = h16x2(ex2f(0.2f * ra), ex2f(0.2f * rb));
            g_hrB[k * (NN / 2) + (row0 + ty * 8) / 2 + i2] = make_uint2(bx, by);
        }
    }
    // ---- fp16 transpose: g_xeT_h[k][f][n] ----
#pragma unroll
    for (int j = 0; j < 4; j++) {
        uint32_t hp[4];
#pragma unroll
        for (int i2 = 0; i2 < 4; i2++)
            hp[i2] = h16x2(acc[2 * i2][j], acc[2 * i2 + 1][j]);
        size_t base = ((size_t)(k * FPD + tx * 4 + j)) * NN + row0 + ty * 8;
        *(uint4*)&g_xeT_h[base] = make_uint4(hp[0], hp[1], hp[2], hp[3]);
    }
}

// ---------------- Kernel C: attention, fp16 mma, 4-stage cp.async pipeline ---
// (R10 kernel + piggybacked float-mask output using idle DRAM bandwidth.)
// p = 2^max(s, 0.2s) = max(A*B, A2*B2); A per-row (regs), B per-m (shfl bcast),
// mask = fp16 0/1 multiplied in. 4 SMEM stages, wait_group 2.
#define MCH 64
#define NCHUNK (NN / MCH)
#define V_STAGE_B  8192     // 64 f-rows x 128B
#define MH_STAGE_B 16384    // 128 n-rows x 128B
#define SMEM_ATTN  (4 * (V_STAGE_B + MH_STAGE_B))   // 96 KB dynamic

__global__ void __launch_bounds__(256, 2) gat_attn_mma(float* __restrict__ out,
                                                       float* __restrict__ mout) {
    extern __shared__ __align__(16) char smem[];
    const uint32_t svb  = smem_u32(smem);                    // 4 x V stages
    const uint32_t smhb = svb + 4 * V_STAGE_B;               // 4 x MH stages

    const int tid  = threadIdx.x;
    const int lane = tid & 31;
    const int warp = tid >> 5;
    const int k    = blockIdx.y;
    const int n0   = blockIdx.x * 128;
    const int g    = lane >> 2;          // 0..7
    const int q    = lane & 3;           // 0..3
    const int r0   = warp * 16 + g;
    const int r1   = r0 + 8;
    const int cid  = blockIdx.y * 32 + blockIdx.x;   // 0..255 (mask-out slice)

    const float hl2_0 = g_hl[k * NN + n0 + r0];
    const float hl2_1 = g_hl[k * NN + n0 + r1];
    const uint32_t Ah0  = h16x2(ex2f(hl2_0), ex2f(hl2_0));
    const uint32_t A2h0 = h16x2(ex2f(0.2f * hl2_0), ex2f(0.2f * hl2_0));
    const uint32_t Ah1  = h16x2(ex2f(hl2_1), ex2f(hl2_1));
    const uint32_t A2h1 = h16x2(ex2f(0.2f * hl2_1), ex2f(0.2f * hl2_1));
    const uint32_t onesB = (lane < 4) ? 0x3C003C00u : 0u;    // rowsum B-fragment

    float d[8][4];
#pragma unroll
    for (int nt = 0; nt < 8; nt++)
#pragma unroll
        for (int e = 0; e < 4; e++) d[nt][e] = 0.0f;
    float drs[4] = {0.f, 0.f, 0.f, 0.f};

    const uint32_t lm_row  = ((lane & 16) >> 1) + (lane & 7);   // 0..15
    const uint32_t lm_koff = (lane & 8) ? 16u : 0u;
    const uint32_t vswz = (uint32_t)(lane & 7) << 4;
    const uint32_t mswz = (uint32_t)g << 4;

    uint2 breg, breg_next;

    auto stage_chunk = [&](int m0, int st) {
#pragma unroll
        for (int u = 0; u < 2; u++) {        // V: 512 x 16B
            int idx = u * 256 + tid;
            int f = idx >> 3, mo8 = (idx & 7) * 8;
            uint32_t dst = svb + st * V_STAGE_B + f * 128
                         + (((uint32_t)mo8 * 2) ^ ((uint32_t)(f & 7) << 4));
            CP16(dst, g_xeT_h + ((size_t)(k * FPD + f)) * NN + m0 + mo8);
        }
#pragma unroll
        for (int u = 0; u < 4; u++) {        // MH: 1024 x 16B
            int idx = u * 256 + tid;
            int row = idx >> 3, c16 = idx & 7;
            uint32_t dst = smhb + st * MH_STAGE_B + row * 128
                         + (((uint32_t)c16 * 16) ^ ((uint32_t)(row & 7) << 4));
            CP16(dst, g_maskh + ((size_t)(n0 + row)) * NN + m0 + c16 * 8);
        }
        CP_COMMIT();
    };

    // ---- prologue: stage chunks 0,1,2 ----
    stage_chunk(0, 0);
    stage_chunk(MCH, 1);
    stage_chunk(2 * MCH, 2);
    breg = g_hrB[k * (NN / 2) + lane];

#pragma unroll 1
    for (int c = 0; c < NCHUNK; c++) {
        const int st = c & 3;
        CP_WAIT(2);
        __syncthreads();
        if (c + 3 < NCHUNK) stage_chunk((c + 3) * MCH, (c + 3) & 3);
        if (c + 1 < NCHUNK) breg_next = g_hrB[k * (NN / 2) + (c + 1) * 32 + lane];

        // ---- piggyback: emit this CTA's slice of the float mask output ----
        if (mout) {
            size_t mbase = (size_t)cid * 65536 + (size_t)c * 1024 + tid * 4;
            uint2 v = *(const uint2*)(g_maskh + mbase);
            float4 f;
            f.x = (v.x & 0xFFFFu) ? 1.0f : 0.0f;
            f.y = (v.x >> 16)     ? 1.0f : 0.0f;
            f.z = (v.y & 0xFFFFu) ? 1.0f : 0.0f;
            f.w = (v.y >> 16)     ? 1.0f : 0.0f;
            *(float4*)(mout + mbase) = f;
        }

        const uint32_t sv   = svb + st * V_STAGE_B;
        const uint32_t mh0b = smhb + st * MH_STAGE_B + r0 * 128;
        const uint32_t mh1b = smhb + st * MH_STAGE_B + r1 * 128;

#pragma unroll
        for (int t = 0; t < 4; t++) {
            const int j = 8 * t + q;
            uint32_t b0x = __shfl_sync(0xFFFFFFFFu, breg.x, j);
            uint32_t b0y = __shfl_sync(0xFFFFFFFFu, breg.y, j);
            uint32_t b1x = __shfl_sync(0xFFFFFFFFu, breg.x, j + 4);
            uint32_t b1y = __shfl_sync(0xFFFFFFFFu, breg.y, j + 4);
            uint32_t moff0 = ((uint32_t)(32 * t + 4 * q)) ^ mswz;
            uint32_t moff1 = moff0 ^ 16u;
            uint32_t mh00 = lds32(mh0b + moff0);
            uint32_t mh01 = lds32(mh0b + moff1);
            uint32_t mh10 = lds32(mh1b + moff0);
            uint32_t mh11 = lds32(mh1b + moff1);
            uint32_t ah0 = hmul2(hmax2(hmul2(Ah0, b0x), hmul2(A2h0, b0y)), mh00);
            uint32_t ah1 = hmul2(hmax2(hmul2(Ah1, b0x), hmul2(A2h1, b0y)), mh10);
            uint32_t ah2 = hmul2(hmax2(hmul2(Ah0, b1x), hmul2(A2h0, b1y)), mh01);
            uint32_t ah3 = hmul2(hmax2(hmul2(Ah1, b1x), hmul2(A2h1, b1y)), mh11);

            const uint32_t voff = ((uint32_t)(32 * t) + lm_koff) ^ vswz;
            uint32_t vA[4], vB[4], vC[4], vD[4];
#pragma unroll
            for (int pr = 0; pr < 4; pr++)
                LDSM4(vA[pr], vB[pr], vC[pr], vD[pr], sv + (pr * 16 + lm_row) * 128 + voff);
#pragma unroll
            for (int pr = 0; pr < 4; pr++) {
                MMAH(d[2 * pr],     ah0, ah1, ah2, ah3, vA[pr], vB[pr]);
                MMAH(d[2 * pr + 1], ah0, ah1, ah2, ah3, vC[pr], vD[pr]);
            }
            MMAH(drs, ah0, ah1, ah2, ah3, onesB, onesB);
        }
        breg = breg_next;
    }

    // ---- epilogue: rowsums from ones-column, normalize, double-ELU, store ----
    const float rv0 = __shfl_sync(0xFFFFFFFFu, drs[0], 0, 4);
    const float rv1 = __shfl_sync(0xFFFFFFFFu, drs[2], 0, 4);
    const float i0 = 1.0f / rv0;
    const float i1 = 1.0f / rv1;
    float* o0p = out + (size_t)(n0 + r0) * KFP + k * FPD + 2 * q;
    float* o1p = out + (size_t)(n0 + r1) * KFP + k * FPD + 2 * q;
#pragma unroll
    for (int nt = 0; nt < 8; nt++) {
        float z0 = d[nt][0] * i0, z1 = d[nt][1] * i0;
        float z2 = d[nt][2] * i1, z3 = d[nt][3] * i1;
        z0 = z0 > 0.f ? z0 : expm1f(z0); z0 = z0 > 0.f ? z0 : expm1f(z0);
        z1 = z1 > 0.f ? z1 : expm1f(z1); z1 = z1 > 0.f ? z1 : expm1f(z1);
        z2 = z2 > 0.f ? z2 : expm1f(z2); z2 = z2 > 0.f ? z2 : expm1f(z2);
        z3 = z3 > 0.f ? z3 : expm1f(z3); z3 = z3 > 0.f ? z3 : expm1f(z3);
        *(float2*)(o0p + nt * 8) = make_float2(z0, z1);
        *(float2*)(o1p + nt * 8) = make_float2(z2, z3);
    }
}

// ---------------- launch -----------------------------------------------------
extern "C" void kernel_launch(void* const* d_in, const int* in_sizes, int n_in,
                              void* d_out, int out_size) {
    const float* x  = (const float*)d_in[0];
    const float* W  = (const float*)d_in[1];
    const float* b  = (const float*)d_in[2];
    const float* al = (const float*)d_in[3];
    const float* ar = (const float*)d_in[4];
    const void*  m  = d_in[5];
    float* out = (float*)d_out;

    cudaFuncSetAttribute(gat_attn_mma, cudaFuncAttributeMaxDynamicSharedMemorySize, SMEM_ATTN);

    const int OUT_ELEMS  = NN * KFP;
    const int MASK_ELEMS = NN * NN;
    float* mout = (out_size >= OUT_ELEMS + MASK_ELEMS) ? (out + OUT_ELEMS) : nullptr;

    fused_gemm_canon<<<256 + CANON_BLKS, 256>>>(x, W, b, al, ar, m);
    gat_attn_mma<<<dim3(32, 8), 256, SMEM_ATTN>>>(out, mout);
}

// round 15
// speedup vs baseline: 1.2150x; 1.2150x over previous
#include <cuda_runtime.h>
#include <cuda_fp16.h>
#include <cstdint>

#define NN   4096
#define FF   256
#define KH   8
#define FPD  64
#define KFP  512   // K*FP
#define LOG2E 1.4426950408889634f

// ---------------- scratch (static device globals; no allocation) -------------
__device__ float g_hl[KH * NN];                   // hl[k][n] * log2(e)
__device__ uint2 g_hrB[KH * NN / 2];              // packed { fp16x2(B,B'), fp16x2(B2,B2') }
__device__ unsigned short g_maskh[NN * NN];       // 32 MB fp16 mask (1.0 / 0.0)
__device__ unsigned short g_xeT_h[KH * FPD * NN]; // 4 MB: fp16(xe)[k][f][n]

// =================== helpers (baseline PTX only) ============================
__device__ __forceinline__ uint32_t smem_u32(const void* p) {
    uint32_t a;
    asm("{ .reg .u64 t; cvta.to.shared.u64 t, %1; cvt.u32.u64 %0, t; }" : "=r"(a) : "l"(p));
    return a;
}
__device__ __forceinline__ uint32_t h16x2(float x, float y) {
    uint32_t r;
    asm("cvt.rn.f16x2.f32 %0, %1, %2;" : "=r"(r) : "f"(y), "f"(x));
    return r;
}
__device__ __forceinline__ float ex2f(float x) {
    float r;
    asm("ex2.approx.ftz.f32 %0, %1;" : "=f"(r) : "f"(x));
    return r;
}
__device__ __forceinline__ uint32_t hmul2(uint32_t a, uint32_t b) {
    uint32_t r;
    asm("mul.f16x2 %0, %1, %2;" : "=r"(r) : "r"(a), "r"(b));
    return r;
}
__device__ __forceinline__ uint32_t hmax2(uint32_t a, uint32_t b) {
    uint32_t r;
    asm("max.f16x2 %0, %1, %2;" : "=r"(r) : "r"(a), "r"(b));
    return r;
}
__device__ __forceinline__ uint32_t lds32(uint32_t a) {
    uint32_t r;
    asm volatile("ld.shared.b32 %0, [%1];" : "=r"(r) : "r"(a));
    return r;
}
#define LDSM4(R0, R1, R2, R3, A) \
    asm volatile("ldmatrix.sync.aligned.m8n8.x4.shared.b16 {%0,%1,%2,%3}, [%4];" \
                 : "=r"(R0), "=r"(R1), "=r"(R2), "=r"(R3) : "r"(A))
#define MMAH(D, A0, A1, A2, A3, B0, B1) \
    asm volatile("mma.sync.aligned.m16n8k16.row.col.f32.f16.f16.f32 " \
                 "{%0,%1,%2,%3}, {%4,%5,%6,%7}, {%8,%9}, {%0,%1,%2,%3};" \
                 : "+f"((D)[0]), "+f"((D)[1]), "+f"((D)[2]), "+f"((D)[3]) \
                 : "r"(A0), "r"(A1), "r"(A2), "r"(A3), "r"(B0), "r"(B1))
#define CP16(dst, src) \
    asm volatile("cp.async.cg.shared.global [%0], [%1], 16;" :: "r"(dst), "l"(src) : "memory")
#define CP_COMMIT() asm volatile("cp.async.commit_group;" ::: "memory")
#define CP_WAIT(n)  asm volatile("cp.async.wait_group %0;" :: "n"(n) : "memory")

// ---------------- Fused kernel: GEMM(+hl/hrB+fp16 transpose) || mask canon ---
// Blocks [0,256): xe GEMM per (row-block, head). Blocks [256, 256+2048):
// mask canon to fp16 0/1 (32 elems/thread). Format detection is per-canon-
// block: 64 uniform head words; words-format <=> all in {0,1,0x3F800000}.
#define CANON_BLKS 2048   // 2048 * 256 thr * 32 elems = 16M = NN*NN

__global__ void __launch_bounds__(256) fused_gemm_canon(
        const float* __restrict__ x, const float* __restrict__ W,
        const float* __restrict__ b, const float* __restrict__ al,
        const float* __restrict__ ar, const void* __restrict__ m) {
    if (blockIdx.x >= 256) {
        // ---- per-block format detection (uniform loads, L1/L2 broadcast) ----
        bool words = true;
        const unsigned int* mw = (const unsigned int*)m;
#pragma unroll 16
        for (int i = 0; i < 64; i++) {
            unsigned int w = mw[i];
            if (w > 1u && w != 0x3F800000u) words = false;
        }
        // ---- canon: 32 elements per thread -> fp16 0/1 ----
        int idx = (blockIdx.x - 256) * 256 + threadIdx.x;   // 0..524287
        int e0 = idx * 32;
        int n  = e0 >> 12;
        int m0 = e0 & 4095;
        uint32_t h[16];
        if (words) {               // 4-byte words (int32 or float32): nonzero test
            const uint4* p = (const uint4*)((const unsigned int*)m + (size_t)n * NN + m0);
#pragma unroll
            for (int i = 0; i < 8; i++) {
                uint4 w = p[i];
                h[2 * i]     = (w.x ? 0x3C00u : 0u) | (w.y ? 0x3C000000u : 0u);
                h[2 * i + 1] = (w.z ? 0x3C00u : 0u) | (w.w ? 0x3C000000u : 0u);
            }
        } else {                   // packed uint8
            const uint4* p = (const uint4*)((const unsigned char*)m + (size_t)n * NN + m0);
            uint4 w01 = p[0], w23 = p[1];
            unsigned wv[8] = {w01.x, w01.y, w01.z, w01.w, w23.x, w23.y, w23.z, w23.w};
#pragma unroll
            for (int i = 0; i < 8; i++) {
                unsigned wq = wv[i];
                h[2 * i]     = ((wq & 0x000000FFu) ? 0x3C00u : 0u) | ((wq & 0x0000FF00u) ? 0x3C000000u : 0u);
                h[2 * i + 1] = ((wq & 0x00FF0000u) ? 0x3C00u : 0u) | ((wq & 0xFF000000u) ? 0x3C000000u : 0u);
            }
        }
        uint4* hdst = (uint4*)(g_maskh + (size_t)n * NN + m0);
#pragma unroll
        for (int i = 0; i < 4; i++)
            hdst[i] = make_uint4(h[4 * i], h[4 * i + 1], h[4 * i + 2], h[4 * i + 3]);
        return;
    }

    // ===================== xe GEMM (blocks 0..255) ==========================
    __shared__ float a_s[16][128];
    __shared__ float b_s[16][64];
    const int gb  = blockIdx.x;
    const int tid = threadIdx.x;
    const int tx = tid & 15;
    const int ty = tid >> 4;
    const int row0 = (gb >> 3) * 128;
    const int k    = gb & 7;              // head
    const int col0 = k * 64;

    float acc[8][4];
#pragma unroll
    for (int i = 0; i < 8; i++)
#pragma unroll
        for (int j = 0; j < 4; j++) acc[i][j] = 0.0f;

    for (int k0 = 0; k0 < FF; k0 += 16) {
#pragma unroll
        for (int u = 0; u < 2; u++) {
            int f4 = tid * 2 + u;
            int r  = f4 >> 2;
            int c4 = f4 & 3;
            float4 v = *(const float4*)&x[(size_t)(row0 + r) * FF + k0 + c4 * 4];
            a_s[c4 * 4 + 0][r] = v.x; a_s[c4 * 4 + 1][r] = v.y;
            a_s[c4 * 4 + 2][r] = v.z; a_s[c4 * 4 + 3][r] = v.w;
        }
        {
            int o  = tid >> 2;
            int c4 = tid & 3;
            float4 v = *(const float4*)&W[(size_t)(col0 + o) * FF + k0 + c4 * 4];
            b_s[c4 * 4 + 0][o] = v.x; b_s[c4 * 4 + 1][o] = v.y;
            b_s[c4 * 4 + 2][o] = v.z; b_s[c4 * 4 + 3][o] = v.w;
        }
        __syncthreads();
#pragma unroll
        for (int kk = 0; kk < 16; kk++) {
            float a_f[8], b_f[4];
#pragma unroll
            for (int i = 0; i < 8; i++) a_f[i] = a_s[kk][ty * 8 + i];
#pragma unroll
            for (int j = 0; j < 4; j++) b_f[j] = b_s[kk][tx * 4 + j];
#pragma unroll
            for (int i = 0; i < 8; i++)
#pragma unroll
                for (int j = 0; j < 4; j++) acc[i][j] += a_f[i] * b_f[j];
        }
        __syncthreads();
    }
    float4 bias = *(const float4*)&b[col0 + tx * 4];
#pragma unroll
    for (int i = 0; i < 8; i++) {
        acc[i][0] += bias.x; acc[i][1] += bias.y;
        acc[i][2] += bias.z; acc[i][3] += bias.w;
    }
    // ---- fused hl/hr: partial dots, butterfly over tx ----
    float4 al4 = *(const float4*)&al[k * FPD + tx * 4];
    float4 ar4 = *(const float4*)&ar[k * FPD + tx * 4];
    float lsum[8], rsum[8];
#pragma unroll
    for (int i = 0; i < 8; i++) {
        float l = acc[i][0] * al4.x + acc[i][1] * al4.y + acc[i][2] * al4.z + acc[i][3] * al4.w;
        float r = acc[i][0] * ar4.x + acc[i][1] * ar4.y + acc[i][2] * ar4.z + acc[i][3] * ar4.w;
#pragma unroll
        for (int off = 8; off; off >>= 1) {
            l += __shfl_xor_sync(0xFFFFFFFFu, l, off);
            r += __shfl_xor_sync(0xFFFFFFFFu, r, off);
        }
        lsum[i] = l; rsum[i] = r;
    }
    if (tx == 0) {
#pragma unroll
        for (int i = 0; i < 8; i++)
            g_hl[k * NN + row0 + ty * 8 + i] = lsum[i] * LOG2E;
#pragma unroll
        for (int i2 = 0; i2 < 4; i2++) {
            float ra = rsum[2 * i2] * LOG2E, rb = rsum[2 * i2 + 1] * LOG2E;
            uint32_t bx = h16x2(ex2f(ra), ex2f(rb));
            uint32_t by = h16x2(ex2f(0.2f * ra), ex2f(0.2f * rb));
            g_hrB[k * (NN / 2) + (row0 + ty * 8) / 2 + i2] = make_uint2(bx, by);
        }
    }
    // ---- fp16 transpose: g_xeT_h[k][f][n] ----
#pragma unroll
    for (int j = 0; j < 4; j++) {
        uint32_t hp[4];
#pragma unroll
        for (int i2 = 0; i2 < 4; i2++)
            hp[i2] = h16x2(acc[2 * i2][j], acc[2 * i2 + 1][j]);
        size_t base = ((size_t)(k * FPD + tx * 4 + j)) * NN + row0 + ty * 8;
        *(uint4*)&g_xeT_h[base] = make_uint4(hp[0], hp[1], hp[2], hp[3]);
    }
}

// ---------------- Kernel C: attention (R10, unchanged) + converter CTAs ------
// Blocks [0,256): the proven R10 attn loop (untouched — R12/R14 showed any
// addition to these warps regresses). Blocks [256,296): 40 converter CTAs
// fill the idle occupancy slots (296 = 148 SM x 2) and stream the fp16 mask
// to the float output using DRAM bandwidth attn leaves idle (6%).
#define MCH 64
#define NCHUNK (NN / MCH)
#define V_STAGE_B  8192     // 64 f-rows x 128B
#define MH_STAGE_B 16384    // 128 n-rows x 128B
#define SMEM_ATTN  (4 * (V_STAGE_B + MH_STAGE_B))   // 96 KB dynamic
#define CONV_BLKS  40
#define ATTN_GRID  (256 + CONV_BLKS)

__global__ void __launch_bounds__(256, 2) gat_attn_mma(float* __restrict__ out,
                                                       float* __restrict__ mout) {
    if (blockIdx.x >= 256) {
        // ================= converter CTAs: fp16 mask -> float ===============
        if (!mout) return;
        const uint32_t step = CONV_BLKS * 256;
        uint32_t u = (blockIdx.x - 256) * 256 + threadIdx.x;
#pragma unroll 4
        for (; u < NN * NN / 4; u += step) {
            uint2 v = *(const uint2*)(g_maskh + (size_t)u * 4);
            float4 f;
            f.x = (v.x & 0xFFFFu) ? 1.0f : 0.0f;
            f.y = (v.x >> 16)     ? 1.0f : 0.0f;
            f.z = (v.y & 0xFFFFu) ? 1.0f : 0.0f;
            f.w = (v.y >> 16)     ? 1.0f : 0.0f;
            *(float4*)(mout + (size_t)u * 4) = f;
        }
        return;
    }

    // ===================== attention (blocks 0..255) ========================
    extern __shared__ __align__(16) char smem[];
    const uint32_t svb  = smem_u32(smem);                    // 4 x V stages
    const uint32_t smhb = svb + 4 * V_STAGE_B;               // 4 x MH stages

    const int tid  = threadIdx.x;
    const int lane = tid & 31;
    const int warp = tid >> 5;
    const int k    = blockIdx.x >> 5;            // head
    const int n0   = (blockIdx.x & 31) * 128;
    const int g    = lane >> 2;          // 0..7
    const int q    = lane & 3;           // 0..3
    const int r0   = warp * 16 + g;
    const int r1   = r0 + 8;

    const float hl2_0 = g_hl[k * NN + n0 + r0];
    const float hl2_1 = g_hl[k * NN + n0 + r1];
    const uint32_t Ah0  = h16x2(ex2f(hl2_0), ex2f(hl2_0));
    const uint32_t A2h0 = h16x2(ex2f(0.2f * hl2_0), ex2f(0.2f * hl2_0));
    const uint32_t Ah1  = h16x2(ex2f(hl2_1), ex2f(hl2_1));
    const uint32_t A2h1 = h16x2(ex2f(0.2f * hl2_1), ex2f(0.2f * hl2_1));
    const uint32_t onesB = (lane < 4) ? 0x3C003C00u : 0u;    // rowsum B-fragment

    float d[8][4];
#pragma unroll
    for (int nt = 0; nt < 8; nt++)
#pragma unroll
        for (int e = 0; e < 4; e++) d[nt][e] = 0.0f;
    float drs[4] = {0.f, 0.f, 0.f, 0.f};

    const uint32_t lm_row  = ((lane & 16) >> 1) + (lane & 7);   // 0..15
    const uint32_t lm_koff = (lane & 8) ? 16u : 0u;
    const uint32_t vswz = (uint32_t)(lane & 7) << 4;
    const uint32_t mswz = (uint32_t)g << 4;

    uint2 breg, breg_next;

    auto stage_chunk = [&](int m0, int st) {
#pragma unroll
        for (int u = 0; u < 2; u++) {        // V: 512 x 16B
            int idx = u * 256 + tid;
            int f = idx >> 3, mo8 = (idx & 7) * 8;
            uint32_t dst = svb + st * V_STAGE_B + f * 128
                         + (((uint32_t)mo8 * 2) ^ ((uint32_t)(f & 7) << 4));
            CP16(dst, g_xeT_h + ((size_t)(k * FPD + f)) * NN + m0 + mo8);
        }
#pragma unroll
        for (int u = 0; u < 4; u++) {        // MH: 1024 x 16B
            int idx = u * 256 + tid;
            int row = idx >> 3, c16 = idx & 7;
            uint32_t dst = smhb + st * MH_STAGE_B + row * 128
                         + (((uint32_t)c16 * 16) ^ ((uint32_t)(row & 7) << 4));
            CP16(dst, g_maskh + ((size_t)(n0 + row)) * NN + m0 + c16 * 8);
        }
        CP_COMMIT();
    };

    // ---- prologue: stage chunks 0,1,2 ----
    stage_chunk(0, 0);
    stage_chunk(MCH, 1);
    stage_chunk(2 * MCH, 2);
    breg = g_hrB[k * (NN / 2) + lane];

#pragma unroll 1
    for (int c = 0; c < NCHUNK; c++) {
        const int st = c & 3;
        CP_WAIT(2);
        __syncthreads();
        if (c + 3 < NCHUNK) stage_chunk((c + 3) * MCH, (c + 3) & 3);
        if (c + 1 < NCHUNK) breg_next = g_hrB[k * (NN / 2) + (c + 1) * 32 + lane];

        const uint32_t sv   = svb + st * V_STAGE_B;
        const uint32_t mh0b = smhb + st * MH_STAGE_B + r0 * 128;
        const uint32_t mh1b = smhb + st * MH_STAGE_B + r1 * 128;

#pragma unroll
        for (int t = 0; t < 4; t++) {
            const int j = 8 * t + q;
            uint32_t b0x = __shfl_sync(0xFFFFFFFFu, breg.x, j);
            uint32_t b0y = __shfl_sync(0xFFFFFFFFu, breg.y, j);
            uint32_t b1x = __shfl_sync(0xFFFFFFFFu, breg.x, j + 4);
            uint32_t b1y = __shfl_sync(0xFFFFFFFFu, breg.y, j + 4);
            uint32_t moff0 = ((uint32_t)(32 * t + 4 * q)) ^ mswz;
            uint32_t moff1 = moff0 ^ 16u;
            uint32_t mh00 = lds32(mh0b + moff0);
            uint32_t mh01 = lds32(mh0b + moff1);
            uint32_t mh10 = lds32(mh1b + moff0);
            uint32_t mh11 = lds32(mh1b + moff1);
            uint32_t ah0 = hmul2(hmax2(hmul2(Ah0, b0x), hmul2(A2h0, b0y)), mh00);
            uint32_t ah1 = hmul2(hmax2(hmul2(Ah1, b0x), hmul2(A2h1, b0y)), mh10);
            uint32_t ah2 = hmul2(hmax2(hmul2(Ah0, b1x), hmul2(A2h0, b1y)), mh01);
            uint32_t ah3 = hmul2(hmax2(hmul2(Ah1, b1x), hmul2(A2h1, b1y)), mh11);

            const uint32_t voff = ((uint32_t)(32 * t) + lm_koff) ^ vswz;
            uint32_t vA[4], vB[4], vC[4], vD[4];
#pragma unroll
            for (int pr = 0; pr < 4; pr++)
                LDSM4(vA[pr], vB[pr], vC[pr], vD[pr], sv + (pr * 16 + lm_row) * 128 + voff);
#pragma unroll
            for (int pr = 0; pr < 4; pr++) {
                MMAH(d[2 * pr],     ah0, ah1, ah2, ah3, vA[pr], vB[pr]);
                MMAH(d[2 * pr + 1], ah0, ah1, ah2, ah3, vC[pr], vD[pr]);
            }
            MMAH(drs, ah0, ah1, ah2, ah3, onesB, onesB);
        }
        breg = breg_next;
    }

    // ---- epilogue: rowsums from ones-column, normalize, double-ELU, store ----
    const float rv0 = __shfl_sync(0xFFFFFFFFu, drs[0], 0, 4);
    const float rv1 = __shfl_sync(0xFFFFFFFFu, drs[2], 0, 4);
    const float i0 = 1.0f / rv0;
    const float i1 = 1.0f / rv1;
    float* o0p = out + (size_t)(n0 + r0) * KFP + k * FPD + 2 * q;
    float* o1p = out + (size_t)(n0 + r1) * KFP + k * FPD + 2 * q;
#pragma unroll
    for (int nt = 0; nt < 8; nt++) {
        float z0 = d[nt][0] * i0, z1 = d[nt][1] * i0;
        float z2 = d[nt][2] * i1, z3 = d[nt][3] * i1;
        z0 = z0 > 0.f ? z0 : expm1f(z0); z0 = z0 > 0.f ? z0 : expm1f(z0);
        z1 = z1 > 0.f ? z1 : expm1f(z1); z1 = z1 > 0.f ? z1 : expm1f(z1);
        z2 = z2 > 0.f ? z2 : expm1f(z2); z2 = z2 > 0.f ? z2 : expm1f(z2);
        z3 = z3 > 0.f ? z3 : expm1f(z3); z3 = z3 > 0.f ? z3 : expm1f(z3);
        *(float2*)(o0p + nt * 8) = make_float2(z0, z1);
        *(float2*)(o1p + nt * 8) = make_float2(z2, z3);
    }
}

// ---------------- launch -----------------------------------------------------
extern "C" void kernel_launch(void* const* d_in, const int* in_sizes, int n_in,
                              void* d_out, int out_size) {
    const float* x  = (const float*)d_in[0];
    const float* W  = (const float*)d_in[1];
    const float* b  = (const float*)d_in[2];
    const float* al = (const float*)d_in[3];
    const float* ar = (const float*)d_in[4];
    const void*  m  = d_in[5];
    float* out = (float*)d_out;

    cudaFuncSetAttribute(gat_attn_mma, cudaFuncAttributeMaxDynamicSharedMemorySize, SMEM_ATTN);

    const int OUT_ELEMS  = NN * KFP;
    const int MASK_ELEMS = NN * NN;
    float* mout = (out_size >= OUT_ELEMS + MASK_ELEMS) ? (out + OUT_ELEMS) : nullptr;

    fused_gemm_canon<<<256 + CANON_BLKS, 256>>>(x, W, b, al, ar, m);
    gat_attn_mma<<<ATTN_GRID, 256, SMEM_ATTN>>>(out, mout);
}

// round 16
// speedup vs baseline: 1.6259x; 1.3383x over previous
#include <cuda_runtime.h>
#include <cuda_fp16.h>
#include <cstdint>

#define NN   4096
#define FF   256
#define KH   8
#define FPD  64
#define KFP  512   // K*FP
#define LOG2E 1.4426950408889634f

// ---------------- scratch (static device globals; no allocation) -------------
__device__ float g_hl[KH * NN];                   // hl[k][n] * log2(e)
__device__ uint2 g_hrB[KH * NN / 2];              // packed { fp16x2(B,B'), fp16x2(B2,B2') }
__device__ unsigned short g_maskh[NN * NN];       // 32 MB fp16 mask (1.0 / 0.0)
__device__ unsigned short g_xeT_h[KH * FPD * NN]; // 4 MB: fp16(xe)[k][f][n]

// =================== helpers (baseline PTX only) ============================
__device__ __forceinline__ uint32_t smem_u32(const void* p) {
    uint32_t a;
    asm("{ .reg .u64 t; cvta.to.shared.u64 t, %1; cvt.u32.u64 %0, t; }" : "=r"(a) : "l"(p));
    return a;
}
__device__ __forceinline__ uint32_t h16x2(float x, float y) {
    uint32_t r;
    asm("cvt.rn.f16x2.f32 %0, %1, %2;" : "=r"(r) : "f"(y), "f"(x));
    return r;
}
__device__ __forceinline__ float ex2f(float x) {
    float r;
    asm("ex2.approx.ftz.f32 %0, %1;" : "=f"(r) : "f"(x));
    return r;
}
__device__ __forceinline__ uint32_t hmul2(uint32_t a, uint32_t b) {
    uint32_t r;
    asm("mul.f16x2 %0, %1, %2;" : "=r"(r) : "r"(a), "r"(b));
    return r;
}
__device__ __forceinline__ uint32_t hmax2(uint32_t a, uint32_t b) {
    uint32_t r;
    asm("max.f16x2 %0, %1, %2;" : "=r"(r) : "r"(a), "r"(b));
    return r;
}
__device__ __forceinline__ uint32_t lds32(uint32_t a) {
    uint32_t r;
    asm volatile("ld.shared.b32 %0, [%1];" : "=r"(r) : "r"(a));
    return r;
}
#define LDSM4(R0, R1, R2, R3, A) \
    asm volatile("ldmatrix.sync.aligned.m8n8.x4.shared.b16 {%0,%1,%2,%3}, [%4];" \
                 : "=r"(R0), "=r"(R1), "=r"(R2), "=r"(R3) : "r"(A))
#define MMAH(D, A0, A1, A2, A3, B0, B1) \
    asm volatile("mma.sync.aligned.m16n8k16.row.col.f32.f16.f16.f32 " \
                 "{%0,%1,%2,%3}, {%4,%5,%6,%7}, {%8,%9}, {%0,%1,%2,%3};" \
                 : "+f"((D)[0]), "+f"((D)[1]), "+f"((D)[2]), "+f"((D)[3]) \
                 : "r"(A0), "r"(A1), "r"(A2), "r"(A3), "r"(B0), "r"(B1))
#define CP16(dst, src) \
    asm volatile("cp.async.cg.shared.global [%0], [%1], 16;" :: "r"(dst), "l"(src) : "memory")
#define CP_COMMIT() asm volatile("cp.async.commit_group;" ::: "memory")
#define CP_WAIT(n)  asm volatile("cp.async.wait_group %0;" :: "n"(n) : "memory")

// fp16x2-pair (uint2) -> float4 of 0/1
__device__ __forceinline__ float4 m2f(uint2 v) {
    float4 f;
    f.x = (v.x & 0xFFFFu) ? 1.0f : 0.0f;
    f.y = (v.x >> 16)     ? 1.0f : 0.0f;
    f.z = (v.y & 0xFFFFu) ? 1.0f : 0.0f;
    f.w = (v.y >> 16)     ? 1.0f : 0.0f;
    return f;
}

// ---------------- Fused kernel: GEMM(+hl/hrB+fp16 transpose) || mask canon ---
// Blocks [0,256): xe GEMM per (row-block, head). Blocks [256, 256+2048):
// mask canon to fp16 0/1 (32 elems/thread). Format detect: thread 0 only
// (32 head words, smem broadcast) — the old all-thread detect cost ~15us of
// chip-wide LSU issue.
#define CANON_BLKS 2048   // 2048 * 256 thr * 32 elems = 16M = NN*NN

__global__ void __launch_bounds__(256) fused_gemm_canon(
        const float* __restrict__ x, const float* __restrict__ W,
        const float* __restrict__ b, const float* __restrict__ al,
        const float* __restrict__ ar, const void* __restrict__ m) {
    if (blockIdx.x >= 256) {
        // ---- detect by thread 0, broadcast (words <=> all in allowed set) ----
        __shared__ int s_words;
        if (threadIdx.x == 0) {
            bool w = true;
            const unsigned int* mw = (const unsigned int*)m;
#pragma unroll
            for (int i = 0; i < 32; i++) {
                unsigned int v = mw[i];
                if (v > 1u && v != 0x3F800000u) w = false;
            }
            s_words = w;
        }
        __syncthreads();
        const bool words = s_words;

        // ---- canon: 32 elements per thread -> fp16 0/1 ----
        int idx = (blockIdx.x - 256) * 256 + threadIdx.x;   // 0..524287
        int e0 = idx * 32;
        int n  = e0 >> 12;
        int m0 = e0 & 4095;
        uint32_t h[16];
        if (words) {               // 4-byte words (int32 or float32): nonzero test
            const uint4* p = (const uint4*)((const unsigned int*)m + (size_t)n * NN + m0);
#pragma unroll
            for (int i = 0; i < 8; i++) {
                uint4 w = p[i];
                h[2 * i]     = (w.x ? 0x3C00u : 0u) | (w.y ? 0x3C000000u : 0u);
                h[2 * i + 1] = (w.z ? 0x3C00u : 0u) | (w.w ? 0x3C000000u : 0u);
            }
        } else {                   // packed uint8
            const uint4* p = (const uint4*)((const unsigned char*)m + (size_t)n * NN + m0);
            uint4 w01 = p[0], w23 = p[1];
            unsigned wv[8] = {w01.x, w01.y, w01.z, w01.w, w23.x, w23.y, w23.z, w23.w};
#pragma unroll
            for (int i = 0; i < 8; i++) {
                unsigned wq = wv[i];
                h[2 * i]     = ((wq & 0x000000FFu) ? 0x3C00u : 0u) | ((wq & 0x0000FF00u) ? 0x3C000000u : 0u);
                h[2 * i + 1] = ((wq & 0x00FF0000u) ? 0x3C00u : 0u) | ((wq & 0xFF000000u) ? 0x3C000000u : 0u);
            }
        }
        uint4* hdst = (uint4*)(g_maskh + (size_t)n * NN + m0);
#pragma unroll
        for (int i = 0; i < 4; i++)
            hdst[i] = make_uint4(h[4 * i], h[4 * i + 1], h[4 * i + 2], h[4 * i + 3]);
        return;
    }

    // ===================== xe GEMM (blocks 0..255) ==========================
    __shared__ float a_s[16][128];
    __shared__ float b_s[16][64];
    const int gb  = blockIdx.x;
    const int tid = threadIdx.x;
    const int tx = tid & 15;
    const int ty = tid >> 4;
    const int row0 = (gb >> 3) * 128;
    const int k    = gb & 7;              // head
    const int col0 = k * 64;

    float acc[8][4];
#pragma unroll
    for (int i = 0; i < 8; i++)
#pragma unroll
        for (int j = 0; j < 4; j++) acc[i][j] = 0.0f;

    for (int k0 = 0; k0 < FF; k0 += 16) {
#pragma unroll
        for (int u = 0; u < 2; u++) {
            int f4 = tid * 2 + u;
            int r  = f4 >> 2;
            int c4 = f4 & 3;
            float4 v = *(const float4*)&x[(size_t)(row0 + r) * FF + k0 + c4 * 4];
            a_s[c4 * 4 + 0][r] = v.x; a_s[c4 * 4 + 1][r] = v.y;
            a_s[c4 * 4 + 2][r] = v.z; a_s[c4 * 4 + 3][r] = v.w;
        }
        {
            int o  = tid >> 2;
            int c4 = tid & 3;
            float4 v = *(const float4*)&W[(size_t)(col0 + o) * FF + k0 + c4 * 4];
            b_s[c4 * 4 + 0][o] = v.x; b_s[c4 * 4 + 1][o] = v.y;
            b_s[c4 * 4 + 2][o] = v.z; b_s[c4 * 4 + 3][o] = v.w;
        }
        __syncthreads();
#pragma unroll
        for (int kk = 0; kk < 16; kk++) {
            float a_f[8], b_f[4];
#pragma unroll
            for (int i = 0; i < 8; i++) a_f[i] = a_s[kk][ty * 8 + i];
#pragma unroll
            for (int j = 0; j < 4; j++) b_f[j] = b_s[kk][tx * 4 + j];
#pragma unroll
            for (int i = 0; i < 8; i++)
#pragma unroll
                for (int j = 0; j < 4; j++) acc[i][j] += a_f[i] * b_f[j];
        }
        __syncthreads();
    }
    float4 bias = *(const float4*)&b[col0 + tx * 4];
#pragma unroll
    for (int i = 0; i < 8; i++) {
        acc[i][0] += bias.x; acc[i][1] += bias.y;
        acc[i][2] += bias.z; acc[i][3] += bias.w;
    }
    // ---- fused hl/hr: partial dots, butterfly over tx ----
    float4 al4 = *(const float4*)&al[k * FPD + tx * 4];
    float4 ar4 = *(const float4*)&ar[k * FPD + tx * 4];
    float lsum[8], rsum[8];
#pragma unroll
    for (int i = 0; i < 8; i++) {
        float l = acc[i][0] * al4.x + acc[i][1] * al4.y + acc[i][2] * al4.z + acc[i][3] * al4.w;
        float r = acc[i][0] * ar4.x + acc[i][1] * ar4.y + acc[i][2] * ar4.z + acc[i][3] * ar4.w;
#pragma unroll
        for (int off = 8; off; off >>= 1) {
            l += __shfl_xor_sync(0xFFFFFFFFu, l, off);
            r += __shfl_xor_sync(0xFFFFFFFFu, r, off);
        }
        lsum[i] = l; rsum[i] = r;
    }
    if (tx == 0) {
#pragma unroll
        for (int i = 0; i < 8; i++)
            g_hl[k * NN + row0 + ty * 8 + i] = lsum[i] * LOG2E;
#pragma unroll
        for (int i2 = 0; i2 < 4; i2++) {
            float ra = rsum[2 * i2] * LOG2E, rb = rsum[2 * i2 + 1] * LOG2E;
            uint32_t bx = h16x2(ex2f(ra), ex2f(rb));
            uint32_t by = h16x2(ex2f(0.2f * ra), ex2f(0.2f * rb));
            g_hrB[k * (NN / 2) + (row0 + ty * 8) / 2 + i2] = make_uint2(bx, by);
        }
    }
    // ---- fp16 transpose: g_xeT_h[k][f][n] ----
#pragma unroll
    for (int j = 0; j < 4; j++) {
        uint32_t hp[4];
#pragma unroll
        for (int i2 = 0; i2 < 4; i2++)
            hp[i2] = h16x2(acc[2 * i2][j], acc[2 * i2 + 1][j]);
        size_t base = ((size_t)(k * FPD + tx * 4 + j)) * NN + row0 + ty * 8;
        *(uint4*)&g_xeT_h[base] = make_uint4(hp[0], hp[1], hp[2], hp[3]);
    }
}

// ---------------- Kernel C: attention (R10 loop) + balanced mask-out ---------
// Blocks [0,256): R10 attn loop untouched; AFTER the loop each CTA converts
// its slice of the float mask (store-issue spread over 2048 warps ~ 8us tail).
// Blocks [256,296): 40 converter CTAs handle the first CONV_UNITS during attn
// (sized to their store-issue budget: 1.5M STG.128 / 320 warps ~ 30us << 84us).
#define MCH 64
#define NCHUNK (NN / MCH)
#define V_STAGE_B  8192     // 64 f-rows x 128B
#define MH_STAGE_B 16384    // 128 n-rows x 128B
#define SMEM_ATTN  (4 * (V_STAGE_B + MH_STAGE_B))   // 96 KB dynamic
#define CONV_BLKS  40
#define ATTN_GRID  (256 + CONV_BLKS)
#define TOT_UNITS  (NN * NN / 4)        // 4M float4-units
#define CONV_UNITS 1572864              // converters: 1.5M units (6M floats)
#define CTA_UNITS  10240                // per attn CTA: (4M-1.5M)/256

__global__ void __launch_bounds__(256, 2) gat_attn_mma(float* __restrict__ out,
                                                       float* __restrict__ mout) {
    const int tid = threadIdx.x;
    if (blockIdx.x >= 256) {
        // ============ converter CTAs: fp16 mask -> float, units [0,CONV) ====
        if (!mout) return;
        const uint32_t step = CONV_BLKS * 256;
        uint32_t u0 = (blockIdx.x - 256) * 256 + tid;
        // MLP-8 batches: 8 loads in flight, then 8 stores
        for (uint32_t u = u0; u < CONV_UNITS; u += step * 8) {
            uint2 v[8];
            float4 f[8];
            int cnt = 0;
#pragma unroll
            for (int i = 0; i < 8; i++) {
                uint32_t uu = u + i * step;
                if (uu < CONV_UNITS) { v[i] = *(const uint2*)(g_maskh + (size_t)uu * 4); cnt = i + 1; }
            }
#pragma unroll
            for (int i = 0; i < 8; i++)
                if (i < cnt) f[i] = m2f(v[i]);
#pragma unroll
            for (int i = 0; i < 8; i++) {
                uint32_t uu = u + i * step;
                if (i < cnt) *(float4*)(mout + (size_t)uu * 4) = f[i];
            }
        }
        return;
    }

    // ===================== attention (blocks 0..255) ========================
    extern __shared__ __align__(16) char smem[];
    const uint32_t svb  = smem_u32(smem);                    // 4 x V stages
    const uint32_t smhb = svb + 4 * V_STAGE_B;               // 4 x MH stages

    const int lane = tid & 31;
    const int warp = tid >> 5;
    const int k    = blockIdx.x >> 5;            // head
    const int n0   = (blockIdx.x & 31) * 128;
    const int g    = lane >> 2;          // 0..7
    const int q    = lane & 3;           // 0..3
    const int r0   = warp * 16 + g;
    const int r1   = r0 + 8;

    const float hl2_0 = g_hl[k * NN + n0 + r0];
    const float hl2_1 = g_hl[k * NN + n0 + r1];
    const uint32_t Ah0  = h16x2(ex2f(hl2_0), ex2f(hl2_0));
    const uint32_t A2h0 = h16x2(ex2f(0.2f * hl2_0), ex2f(0.2f * hl2_0));
    const uint32_t Ah1  = h16x2(ex2f(hl2_1), ex2f(hl2_1));
    const uint32_t A2h1 = h16x2(ex2f(0.2f * hl2_1), ex2f(0.2f * hl2_1));
    const uint32_t onesB = (lane < 4) ? 0x3C003C00u : 0u;    // rowsum B-fragment

    float d[8][4];
#pragma unroll
    for (int nt = 0; nt < 8; nt++)
#pragma unroll
        for (int e = 0; e < 4; e++) d[nt][e] = 0.0f;
    float drs[4] = {0.f, 0.f, 0.f, 0.f};

    const uint32_t lm_row  = ((lane & 16) >> 1) + (lane & 7);   // 0..15
    const uint32_t lm_koff = (lane & 8) ? 16u : 0u;
    const uint32_t vswz = (uint32_t)(lane & 7) << 4;
    const uint32_t mswz = (uint32_t)g << 4;

    uint2 breg, breg_next;

    auto stage_chunk = [&](int m0, int st) {
#pragma unroll
        for (int u = 0; u < 2; u++) {        // V: 512 x 16B
            int idx = u * 256 + tid;
            int f = idx >> 3, mo8 = (idx & 7) * 8;
            uint32_t dst = svb + st * V_STAGE_B + f * 128
                         + (((uint32_t)mo8 * 2) ^ ((uint32_t)(f & 7) << 4));
            CP16(dst, g_xeT_h + ((size_t)(k * FPD + f)) * NN + m0 + mo8);
        }
#pragma unroll
        for (int u = 0; u < 4; u++) {        // MH: 1024 x 16B
            int idx = u * 256 + tid;
            int row = idx >> 3, c16 = idx & 7;
            uint32_t dst = smhb + st * MH_STAGE_B + row * 128
                         + (((uint32_t)c16 * 16) ^ ((uint32_t)(row & 7) << 4));
            CP16(dst, g_maskh + ((size_t)(n0 + row)) * NN + m0 + c16 * 8);
        }
        CP_COMMIT();
    };

    // ---- prologue: stage chunks 0,1,2 ----
    stage_chunk(0, 0);
    stage_chunk(MCH, 1);
    stage_chunk(2 * MCH, 2);
    breg = g_hrB[k * (NN / 2) + lane];

#pragma unroll 1
    for (int c = 0; c < NCHUNK; c++) {
        const int st = c & 3;
        CP_WAIT(2);
        __syncthreads();
        if (c + 3 < NCHUNK) stage_chunk((c + 3) * MCH, (c + 3) & 3);
        if (c + 1 < NCHUNK) breg_next = g_hrB[k * (NN / 2) + (c + 1) * 32 + lane];

        const uint32_t sv   = svb + st * V_STAGE_B;
        const uint32_t mh0b = smhb + st * MH_STAGE_B + r0 * 128;
        const uint32_t mh1b = smhb + st * MH_STAGE_B + r1 * 128;

#pragma unroll
        for (int t = 0; t < 4; t++) {
            const int j = 8 * t + q;
            uint32_t b0x = __shfl_sync(0xFFFFFFFFu, breg.x, j);
            uint32_t b0y = __shfl_sync(0xFFFFFFFFu, breg.y, j);
            uint32_t b1x = __shfl_sync(0xFFFFFFFFu, breg.x, j + 4);
            uint32_t b1y = __shfl_sync(0xFFFFFFFFu, breg.y, j + 4);
            uint32_t moff0 = ((uint32_t)(32 * t + 4 * q)) ^ mswz;
            uint32_t moff1 = moff0 ^ 16u;
            uint32_t mh00 = lds32(mh0b + moff0);
            uint32_t mh01 = lds32(mh0b + moff1);
            uint32_t mh10 = lds32(mh1b + moff0);
            uint32_t mh11 = lds32(mh1b + moff1);
            uint32_t ah0 = hmul2(hmax2(hmul2(Ah0, b0x), hmul2(A2h0, b0y)), mh00);
            uint32_t ah1 = hmul2(hmax2(hmul2(Ah1, b0x), hmul2(A2h1, b0y)), mh10);
            uint32_t ah2 = hmul2(hmax2(hmul2(Ah0, b1x), hmul2(A2h0, b1y)), mh01);
            uint32_t ah3 = hmul2(hmax2(hmul2(Ah1, b1x), hmul2(A2h1, b1y)), mh11);

            const uint32_t voff = ((uint32_t)(32 * t) + lm_koff) ^ vswz;
            uint32_t vA[4], vB[4], vC[4], vD[4];
#pragma unroll
            for (int pr = 0; pr < 4; pr++)
                LDSM4(vA[pr], vB[pr], vC[pr], vD[pr], sv + (pr * 16 + lm_row) * 128 + voff);
#pragma unroll
            for (int pr = 0; pr < 4; pr++) {
                MMAH(d[2 * pr],     ah0, ah1, ah2, ah3, vA[pr], vB[pr]);
                MMAH(d[2 * pr + 1], ah0, ah1, ah2, ah3, vC[pr], vD[pr]);
            }
            MMAH(drs, ah0, ah1, ah2, ah3, onesB, onesB);
        }
        breg = breg_next;
    }

    // ---- epilogue: rowsums from ones-column, normalize, double-ELU, store ----
    const float rv0 = __shfl_sync(0xFFFFFFFFu, drs[0], 0, 4);
    const float rv1 = __shfl_sync(0xFFFFFFFFu, drs[2], 0, 4);
    const float i0 = 1.0f / rv0;
    const float i1 = 1.0f / rv1;
    float* o0p = out + (size_t)(n0 + r0) * KFP + k * FPD + 2 * q;
    float* o1p = out + (size_t)(n0 + r1) * KFP + k * FPD + 2 * q;
#pragma unroll
    for (int nt = 0; nt < 8; nt++) {
        float z0 = d[nt][0] * i0, z1 = d[nt][1] * i0;
        float z2 = d[nt][2] * i1, z3 = d[nt][3] * i1;
        z0 = z0 > 0.f ? z0 : expm1f(z0); z0 = z0 > 0.f ? z0 : expm1f(z0);
        z1 = z1 > 0.f ? z1 : expm1f(z1); z1 = z1 > 0.f ? z1 : expm1f(z1);
        z2 = z2 > 0.f ? z2 : expm1f(z2); z2 = z2 > 0.f ? z2 : expm1f(z2);
        z3 = z3 > 0.f ? z3 : expm1f(z3); z3 = z3 > 0.f ? z3 : expm1f(z3);
        *(float2*)(o0p + nt * 8) = make_float2(z0, z1);
        *(float2*)(o1p + nt * 8) = make_float2(z2, z3);
    }

    // ---- post-loop: this CTA's slice of the float mask output --------------
    if (mout) {
        const int cid = blockIdx.x;
        uint32_t base = CONV_UNITS + (uint32_t)cid * CTA_UNITS;   // 10240 units
#pragma unroll 1
        for (int i = 0; i < CTA_UNITS / 256; i += 8) {            // 40 iters, batched 8
            uint2 v[8];
#pragma unroll
            for (int e = 0; e < 8; e++) {
                uint32_t u = base + (uint32_t)(i + e) * 256 + tid;
                v[e] = *(const uint2*)(g_maskh + (size_t)u * 4);
            }
#pragma unroll
            for (int e = 0; e < 8; e++) {
                uint32_t u = base + (uint32_t)(i + e) * 256 + tid;
                *(float4*)(mout + (size_t)u * 4) = m2f(v[e]);
            }
        }
    }
}

// ---------------- launch -----------------------------------------------------
extern "C" void kernel_launch(void* const* d_in, const int* in_sizes, int n_in,
                              void* d_out, int out_size) {
    const float* x  = (const float*)d_in[0];
    const float* W  = (const float*)d_in[1];
    const float* b  = (const float*)d_in[2];
    const float* al = (const float*)d_in[3];
    const float* ar = (const float*)d_in[4];
    const void*  m  = d_in[5];
    float* out = (float*)d_out;

    cudaFuncSetAttribute(gat_attn_mma, cudaFuncAttributeMaxDynamicSharedMemorySize, SMEM_ATTN);

    const int OUT_ELEMS  = NN * KFP;
    const int MASK_ELEMS = NN * NN;
    float* mout = (out_size >= OUT_ELEMS + MASK_ELEMS) ? (out + OUT_ELEMS) : nullptr;

    fused_gemm_canon<<<256 + CANON_BLKS, 256>>>(x, W, b, al, ar, m);
    gat_attn_mma<<<ATTN_GRID, 256, SMEM_ATTN>>>(out, mout);
}

// round 17
// speedup vs baseline: 1.8481x; 1.1366x over previous
#include <cuda_runtime.h>
#include <cuda_fp16.h>
#include <cstdint>

#define NN   4096
#define FF   256
#define KH   8
#define FPD  64
#define KFP  512   // K*FP
#define LOG2E 1.4426950408889634f

// ---------------- scratch (static device globals; no allocation) -------------
__device__ float g_hl[KH * NN];                   // hl[k][n] * log2(e)
__device__ uint2 g_hrB[KH * NN / 2];              // packed { fp16x2(B,B'), fp16x2(B2,B2') }
__device__ unsigned short g_maskh[NN * NN];       // 32 MB fp16 mask (1.0 / 0.0)
__device__ unsigned short g_xeT_h[KH * FPD * NN]; // 4 MB: fp16(xe)[k][f][n]

// =================== helpers (baseline PTX only) ============================
__device__ __forceinline__ uint32_t smem_u32(const void* p) {
    uint32_t a;
    asm("{ .reg .u64 t; cvta.to.shared.u64 t, %1; cvt.u32.u64 %0, t; }" : "=r"(a) : "l"(p));
    return a;
}
__device__ __forceinline__ uint32_t h16x2(float x, float y) {
    uint32_t r;
    asm("cvt.rn.f16x2.f32 %0, %1, %2;" : "=r"(r) : "f"(y), "f"(x));
    return r;
}
__device__ __forceinline__ unsigned short f2h(float f) {
    unsigned short r;
    asm("cvt.rn.f16.f32 %0, %1;" : "=h"(r) : "f"(f));
    return r;
}
__device__ __forceinline__ uint32_t bf16x2lo(float x, float y) {   // lo=x, hi=y
    uint32_t r;
    asm("cvt.rn.bf16x2.f32 %0, %1, %2;" : "=r"(r) : "f"(y), "f"(x));
    return r;
}
__device__ __forceinline__ float ex2f(float x) {
    float r;
    asm("ex2.approx.ftz.f32 %0, %1;" : "=f"(r) : "f"(x));
    return r;
}
__device__ __forceinline__ uint32_t hmul2(uint32_t a, uint32_t b) {
    uint32_t r;
    asm("mul.f16x2 %0, %1, %2;" : "=r"(r) : "r"(a), "r"(b));
    return r;
}
__device__ __forceinline__ uint32_t hmax2(uint32_t a, uint32_t b) {
    uint32_t r;
    asm("max.f16x2 %0, %1, %2;" : "=r"(r) : "r"(a), "r"(b));
    return r;
}
__device__ __forceinline__ uint32_t lds32(uint32_t a) {
    uint32_t r;
    asm volatile("ld.shared.b32 %0, [%1];" : "=r"(r) : "r"(a));
    return r;
}
#define STS64(A, X, Y) \
    asm volatile("st.shared.v2.b32 [%0], {%1,%2};" :: "r"(A), "r"(X), "r"(Y) : "memory")
#define STSH(A, H) \
    asm volatile("st.shared.b16 [%0], %1;" :: "r"(A), "h"(H) : "memory")
#define LDSM4(R0, R1, R2, R3, A) \
    asm volatile("ldmatrix.sync.aligned.m8n8.x4.shared.b16 {%0,%1,%2,%3}, [%4];" \
                 : "=r"(R0), "=r"(R1), "=r"(R2), "=r"(R3) : "r"(A))
#define MMAH(D, A0, A1, A2, A3, B0, B1) \
    asm volatile("mma.sync.aligned.m16n8k16.row.col.f32.f16.f16.f32 " \
                 "{%0,%1,%2,%3}, {%4,%5,%6,%7}, {%8,%9}, {%0,%1,%2,%3};" \
                 : "+f"((D)[0]), "+f"((D)[1]), "+f"((D)[2]), "+f"((D)[3]) \
                 : "r"(A0), "r"(A1), "r"(A2), "r"(A3), "r"(B0), "r"(B1))
#define MMAB(D, A0, A1, A2, A3, B0, B1) \
    asm volatile("mma.sync.aligned.m16n8k16.row.col.f32.bf16.bf16.f32 " \
                 "{%0,%1,%2,%3}, {%4,%5,%6,%7}, {%8,%9}, {%0,%1,%2,%3};" \
                 : "+f"((D)[0]), "+f"((D)[1]), "+f"((D)[2]), "+f"((D)[3]) \
                 : "r"(A0), "r"(A1), "r"(A2), "r"(A3), "r"(B0), "r"(B1))
#define CP16(dst, src) \
    asm volatile("cp.async.cg.shared.global [%0], [%1], 16;" :: "r"(dst), "l"(src) : "memory")
#define CP_COMMIT() asm volatile("cp.async.commit_group;" ::: "memory")
#define CP_WAIT(n)  asm volatile("cp.async.wait_group %0;" :: "n"(n) : "memory")

// fp16x2-pair (uint2) -> float4 of 0/1
__device__ __forceinline__ float4 m2f(uint2 v) {
    float4 f;
    f.x = (v.x & 0xFFFFu) ? 1.0f : 0.0f;
    f.y = (v.x >> 16)     ? 1.0f : 0.0f;
    f.z = (v.y & 0xFFFFu) ? 1.0f : 0.0f;
    f.w = (v.y >> 16)     ? 1.0f : 0.0f;
    return f;
}

// ---------------- Fused kernel: MMA GEMM(+hl/hrB+fp16 xe) || mask canon ------
// Blocks [0,256): split-bf16 tensor-core GEMM, 128 rows x 1 head per CTA.
//   xe = x@W^T + b via 3-term bf16 MMA (hi*hi + hi*lo + lo*hi, err ~2^-16).
// Blocks [256,256+2048): mask canon to fp16 0/1 (32 elems/thread).
#define CANON_BLKS 2048

__global__ void __launch_bounds__(256) fused_gemm_canon(
        const float* __restrict__ x, const float* __restrict__ W,
        const float* __restrict__ b, const float* __restrict__ al,
        const float* __restrict__ ar, const void* __restrict__ m) {
    __shared__ __align__(16) unsigned short s_xh[128 * 64];  // 16KB (reused as xe^T fp16)
    __shared__ __align__(16) unsigned short s_xl[128 * 64];  // 16KB
    __shared__ __align__(16) unsigned short s_wh[64 * 64];   // 8KB
    __shared__ __align__(16) unsigned short s_wl[64 * 64];   // 8KB

    const int tid  = threadIdx.x;
    const int lane = tid & 31;

    if (blockIdx.x >= 256) {
        // ---- format detect: 1 word/lane + ballot (words <=> all allowed) ----
        unsigned int w0 = ((const unsigned int*)m)[lane];
        bool bad = (w0 > 1u && w0 != 0x3F800000u);
        const bool words = (__ballot_sync(0xFFFFFFFFu, bad) == 0u);

        int idx = (blockIdx.x - 256) * 256 + tid;   // 0..524287
        int e0 = idx * 32;
        int n  = e0 >> 12;
        int m0 = e0 & 4095;
        uint32_t h[16];
        if (words) {
            const uint4* p = (const uint4*)((const unsigned int*)m + (size_t)n * NN + m0);
#pragma unroll
            for (int i = 0; i < 8; i++) {
                uint4 w = p[i];
                h[2 * i]     = (w.x ? 0x3C00u : 0u) | (w.y ? 0x3C000000u : 0u);
                h[2 * i + 1] = (w.z ? 0x3C00u : 0u) | (w.w ? 0x3C000000u : 0u);
            }
        } else {
            const uint4* p = (const uint4*)((const unsigned char*)m + (size_t)n * NN + m0);
            uint4 w01 = p[0], w23 = p[1];
            unsigned wv[8] = {w01.x, w01.y, w01.z, w01.w, w23.x, w23.y, w23.z, w23.w};
#pragma unroll
            for (int i = 0; i < 8; i++) {
                unsigned wq = wv[i];
                h[2 * i]     = ((wq & 0x000000FFu) ? 0x3C00u : 0u) | ((wq & 0x0000FF00u) ? 0x3C000000u : 0u);
                h[2 * i + 1] = ((wq & 0x00FF0000u) ? 0x3C00u : 0u) | ((wq & 0xFF000000u) ? 0x3C000000u : 0u);
            }
        }
        uint4* hdst = (uint4*)(g_maskh + (size_t)n * NN + m0);
#pragma unroll
        for (int i = 0; i < 4; i++)
            hdst[i] = make_uint4(h[4 * i], h[4 * i + 1], h[4 * i + 2], h[4 * i + 3]);
        return;
    }

    // ===================== MMA GEMM (blocks 0..255) =========================
    const int wid  = tid >> 5;
    const int gb   = blockIdx.x;
    const int row0 = (gb >> 3) * 128;
    const int k    = gb & 7;

    const uint32_t sxh = smem_u32(s_xh), sxl = smem_u32(s_xl);
    const uint32_t swh = smem_u32(s_wh), swl = smem_u32(s_wl);

    // fragment lane mappings (A row-major m16k16; B col-major n8k16 — the
    // B mapping is byte-identical to the attn kernel's verified V path)
    const uint32_t lmA_r = lane & 15;
    const uint32_t lmA_k = (lane & 16) ? 16u : 0u;
    const uint32_t lmB_r = ((lane & 16) >> 1) + (lane & 7);
    const uint32_t lmB_k = (lane & 8) ? 16u : 0u;

    float d[8][4];
#pragma unroll
    for (int nt = 0; nt < 8; nt++)
#pragma unroll
        for (int e = 0; e < 4; e++) d[nt][e] = 0.0f;

#pragma unroll 1
    for (int kc = 0; kc < 4; kc++) {
        __syncthreads();
        // ---- stage x chunk 128x64 fp32 -> bf16 hi/lo (swizzled) ----
#pragma unroll
        for (int u = 0; u < 8; u++) {
            int blk = u * 256 + tid;           // 0..2047 float4 blocks
            int r = blk >> 4, c4 = blk & 15;
            float4 v = *(const float4*)&x[(size_t)(row0 + r) * FF + kc * 64 + c4 * 4];
            uint32_t b0 = __float_as_uint(v.x), b1 = __float_as_uint(v.y);
            uint32_t b2 = __float_as_uint(v.z), b3 = __float_as_uint(v.w);
            uint32_t h0 = __byte_perm(b0, b1, 0x7632);
            uint32_t h1 = __byte_perm(b2, b3, 0x7632);
            uint32_t l0 = bf16x2lo(v.x - __uint_as_float(b0 & 0xFFFF0000u),
                                   v.y - __uint_as_float(b1 & 0xFFFF0000u));
            uint32_t l1 = bf16x2lo(v.z - __uint_as_float(b2 & 0xFFFF0000u),
                                   v.w - __uint_as_float(b3 & 0xFFFF0000u));
            uint32_t off = (uint32_t)r * 128 + (((uint32_t)c4 * 8) ^ ((uint32_t)(r & 7) << 4));
            STS64(sxh + off, h0, h1);
            STS64(sxl + off, l0, l1);
        }
        // ---- stage W chunk 64x64 fp32 -> bf16 hi/lo (swizzled) ----
#pragma unroll
        for (int u = 0; u < 4; u++) {
            int blk = u * 256 + tid;           // 0..1023
            int r = blk >> 4, c4 = blk & 15;
            float4 v = *(const float4*)&W[(size_t)(k * 64 + r) * FF + kc * 64 + c4 * 4];
            uint32_t b0 = __float_as_uint(v.x), b1 = __float_as_uint(v.y);
            uint32_t b2 = __float_as_uint(v.z), b3 = __float_as_uint(v.w);
            uint32_t h0 = __byte_perm(b0, b1, 0x7632);
            uint32_t h1 = __byte_perm(b2, b3, 0x7632);
            uint32_t l0 = bf16x2lo(v.x - __uint_as_float(b0 & 0xFFFF0000u),
                                   v.y - __uint_as_float(b1 & 0xFFFF0000u));
            uint32_t l1 = bf16x2lo(v.z - __uint_as_float(b2 & 0xFFFF0000u),
                                   v.w - __uint_as_float(b3 & 0xFFFF0000u));
            uint32_t off = (uint32_t)r * 128 + (((uint32_t)c4 * 8) ^ ((uint32_t)(r & 7) << 4));
            STS64(swh + off, h0, h1);
            STS64(swl + off, l0, l1);
        }
        __syncthreads();

        // ---- 4 k16 steps: 3-pass split-bf16 MMA ----
#pragma unroll
        for (int ks = 0; ks < 4; ks++) {
            uint32_t abase = (uint32_t)(wid * 16 + lmA_r) * 128
                           + (((uint32_t)(ks * 32) + lmA_k) ^ ((lmA_r & 7) << 4));
            uint32_t ah0, ah1, ah2, ah3, al0, al1, al2, al3;
            LDSM4(ah0, ah1, ah2, ah3, sxh + abase);
            LDSM4(al0, al1, al2, al3, sxl + abase);
            uint32_t bA[4], bB[4], bC[4], bD[4];
            uint32_t bbase[4];
#pragma unroll
            for (int p = 0; p < 4; p++) {
                bbase[p] = (uint32_t)(p * 16 + lmB_r) * 128
                         + (((uint32_t)(ks * 32) + lmB_k) ^ ((lmB_r & 7) << 4));
                LDSM4(bA[p], bB[p], bC[p], bD[p], swh + bbase[p]);
            }
            // pass 1: hi*hi
#pragma unroll
            for (int p = 0; p < 4; p++) {
                MMAB(d[2 * p],     ah0, ah1, ah2, ah3, bA[p], bB[p]);
                MMAB(d[2 * p + 1], ah0, ah1, ah2, ah3, bC[p], bD[p]);
            }
            // pass 2: lo*hi  (B-hi frags still live)
#pragma unroll
            for (int p = 0; p < 4; p++) {
                MMAB(d[2 * p],     al0, al1, al2, al3, bA[p], bB[p]);
                MMAB(d[2 * p + 1], al0, al1, al2, al3, bC[p], bD[p]);
            }
            // reload as B-lo, pass 3: hi*lo
#pragma unroll
            for (int p = 0; p < 4; p++)
                LDSM4(bA[p], bB[p], bC[p], bD[p], swl + bbase[p]);
#pragma unroll
            for (int p = 0; p < 4; p++) {
                MMAB(d[2 * p],     ah0, ah1, ah2, ah3, bA[p], bB[p]);
                MMAB(d[2 * p + 1], ah0, ah1, ah2, ah3, bC[p], bD[p]);
            }
        }
    }

    // ===================== epilogue =========================================
    const int g = lane >> 2, q = lane & 3;
    // bias
#pragma unroll
    for (int nt = 0; nt < 8; nt++) {
        float2 b2 = *(const float2*)&b[k * 64 + nt * 8 + 2 * q];
        d[nt][0] += b2.x; d[nt][1] += b2.y;
        d[nt][2] += b2.x; d[nt][3] += b2.y;
    }
    // hl/hr dot products (per-lane partials over its 16 cols, quad-reduce)
    float hl0 = 0.f, hr0 = 0.f, hl1 = 0.f, hr1 = 0.f;
#pragma unroll
    for (int nt = 0; nt < 8; nt++) {
        float2 a2 = *(const float2*)&al[k * 64 + nt * 8 + 2 * q];
        float2 r2 = *(const float2*)&ar[k * 64 + nt * 8 + 2 * q];
        hl0 += d[nt][0] * a2.x + d[nt][1] * a2.y;
        hr0 += d[nt][0] * r2.x + d[nt][1] * r2.y;
        hl1 += d[nt][2] * a2.x + d[nt][3] * a2.y;
        hr1 += d[nt][2] * r2.x + d[nt][3] * r2.y;
    }
#pragma unroll
    for (int off = 1; off <= 2; off <<= 1) {
        hl0 += __shfl_xor_sync(0xFFFFFFFFu, hl0, off);
        hr0 += __shfl_xor_sync(0xFFFFFFFFu, hr0, off);
        hl1 += __shfl_xor_sync(0xFFFFFFFFu, hl1, off);
        hr1 += __shfl_xor_sync(0xFFFFFFFFu, hr1, off);
    }
    // pair partner (row g^1) for hrB packing
    float hrN0 = __shfl_xor_sync(0xFFFFFFFFu, hr0, 4);
    float hrN1 = __shfl_xor_sync(0xFFFFFFFFu, hr1, 4);
    const int ra = row0 + wid * 16 + g;          // row for (hl0, hr0)
    if (q == 0) {
        g_hl[k * NN + ra]     = hl0 * LOG2E;
        g_hl[k * NN + ra + 8] = hl1 * LOG2E;
        if ((g & 1) == 0) {
            float e0 = hr0 * LOG2E, e1 = hrN0 * LOG2E;
            g_hrB[k * (NN / 2) + ra / 2] =
                make_uint2(h16x2(ex2f(e0), ex2f(e1)),
                           h16x2(ex2f(0.2f * e0), ex2f(0.2f * e1)));
            float f0 = hr1 * LOG2E, f1 = hrN1 * LOG2E;
            g_hrB[k * (NN / 2) + (ra + 8) / 2] =
                make_uint2(h16x2(ex2f(f0), ex2f(f1)),
                           h16x2(ex2f(0.2f * f0), ex2f(0.2f * f1)));
        }
    }
    // xe -> fp16 transpose via smem (reuse s_xh as [64 f][128 n] fp16)
    __syncthreads();
    unsigned short* s_t = s_xh;
#pragma unroll
    for (int nt = 0; nt < 8; nt++) {
        int c = nt * 8 + 2 * q;
        int r = wid * 16 + g;
        s_t[c * 128 + r]           = f2h(d[nt][0]);
        s_t[(c + 1) * 128 + r]     = f2h(d[nt][1]);
        s_t[c * 128 + r + 8]       = f2h(d[nt][2]);
        s_t[(c + 1) * 128 + r + 8] = f2h(d[nt][3]);
    }
    __syncthreads();
#pragma unroll
    for (int u = 0; u < 4; u++) {
        int idx = u * 256 + tid;               // 0..1023 uint4
        int f = idx >> 4, c16 = idx & 15;
        uint4 v = *(const uint4*)&s_t[f * 128 + c16 * 8];
        *(uint4*)&g_xeT_h[(size_t)(k * FPD + f) * NN + row0 + c16 * 8] = v;
    }
}

// ---------------- Kernel C: attention (R10 loop) + balanced mask-out ---------
#define MCH 64
#define NCHUNK (NN / MCH)
#define V_STAGE_B  8192
#define MH_STAGE_B 16384
#define SMEM_ATTN  (4 * (V_STAGE_B + MH_STAGE_B))   // 96 KB dynamic
#define CONV_BLKS  40
#define ATTN_GRID  (256 + CONV_BLKS)
#define CONV_UNITS 2621440u             // converters: 2.5M float4-units
#define CTA_UNITS  6144u                // per attn CTA: (4M-2.5M)/256

__global__ void __launch_bounds__(256, 2) gat_attn_mma(float* __restrict__ out,
                                                       float* __restrict__ mout) {
    const int tid = threadIdx.x;
    if (blockIdx.x >= 256) {
        if (!mout) return;
        const uint32_t step = CONV_BLKS * 256;
        uint32_t u0 = (blockIdx.x - 256) * 256 + tid;
        for (uint32_t u = u0; u < CONV_UNITS; u += step * 8) {
            uint2 v[8];
            float4 f[8];
            int cnt = 0;
#pragma unroll
            for (int i = 0; i < 8; i++) {
                uint32_t uu = u + i * step;
                if (uu < CONV_UNITS) { v[i] = *(const uint2*)(g_maskh + (size_t)uu * 4); cnt = i + 1; }
            }
#pragma unroll
            for (int i = 0; i < 8; i++)
                if (i < cnt) f[i] = m2f(v[i]);
#pragma unroll
            for (int i = 0; i < 8; i++) {
                uint32_t uu = u + i * step;
                if (i < cnt) *(float4*)(mout + (size_t)uu * 4) = f[i];
            }
        }
        return;
    }

    extern __shared__ __align__(16) char smem[];
    const uint32_t svb  = smem_u32(smem);
    const uint32_t smhb = svb + 4 * V_STAGE_B;

    const int lane = tid & 31;
    const int warp = tid >> 5;
    const int k    = blockIdx.x >> 5;
    const int n0   = (blockIdx.x & 31) * 128;
    const int g    = lane >> 2;
    const int q    = lane & 3;
    const int r0   = warp * 16 + g;
    const int r1   = r0 + 8;

    const float hl2_0 = g_hl[k * NN + n0 + r0];
    const float hl2_1 = g_hl[k * NN + n0 + r1];
    const uint32_t Ah0  = h16x2(ex2f(hl2_0), ex2f(hl2_0));
    const uint32_t A2h0 = h16x2(ex2f(0.2f * hl2_0), ex2f(0.2f * hl2_0));
    const uint32_t Ah1  = h16x2(ex2f(hl2_1), ex2f(hl2_1));
    const uint32_t A2h1 = h16x2(ex2f(0.2f * hl2_1), ex2f(0.2f * hl2_1));
    const uint32_t onesB = (lane < 4) ? 0x3C003C00u : 0u;

    float d[8][4];
#pragma unroll
    for (int nt = 0; nt < 8; nt++)
#pragma unroll
        for (int e = 0; e < 4; e++) d[nt][e] = 0.0f;
    float drs[4] = {0.f, 0.f, 0.f, 0.f};

    const uint32_t lm_row  = ((lane & 16) >> 1) + (lane & 7);
    const uint32_t lm_koff = (lane & 8) ? 16u : 0u;
    const uint32_t vswz = (uint32_t)(lane & 7) << 4;
    const uint32_t mswz = (uint32_t)g << 4;

    uint2 breg, breg_next;

    auto stage_chunk = [&](int m0, int st) {
#pragma unroll
        for (int u = 0; u < 2; u++) {
            int idx = u * 256 + tid;
            int f = idx >> 3, mo8 = (idx & 7) * 8;
            uint32_t dst = svb + st * V_STAGE_B + f * 128
                         + (((uint32_t)mo8 * 2) ^ ((uint32_t)(f & 7) << 4));
            CP16(dst, g_xeT_h + ((size_t)(k * FPD + f)) * NN + m0 + mo8);
        }
#pragma unroll
        for (int u = 0; u < 4; u++) {
            int idx = u * 256 + tid;
            int row = idx >> 3, c16 = idx & 7;
            uint32_t dst = smhb + st * MH_STAGE_B + row * 128
                         + (((uint32_t)c16 * 16) ^ ((uint32_t)(row & 7) << 4));
            CP16(dst, g_maskh + ((size_t)(n0 + row)) * NN + m0 + c16 * 8);
        }
        CP_COMMIT();
    };

    stage_chunk(0, 0);
    stage_chunk(MCH, 1);
    stage_chunk(2 * MCH, 2);
    breg = g_hrB[k * (NN / 2) + lane];

#pragma unroll 1
    for (int c = 0; c < NCHUNK; c++) {
        const int st = c & 3;
        CP_WAIT(2);
        __syncthreads();
        if (c + 3 < NCHUNK) stage_chunk((c + 3) * MCH, (c + 3) & 3);
        if (c + 1 < NCHUNK) breg_next = g_hrB[k * (NN / 2) + (c + 1) * 32 + lane];

        const uint32_t sv   = svb + st * V_STAGE_B;
        const uint32_t mh0b = smhb + st * MH_STAGE_B + r0 * 128;
        const uint32_t mh1b = smhb + st * MH_STAGE_B + r1 * 128;

#pragma unroll
        for (int t = 0; t < 4; t++) {
            const int j = 8 * t + q;
            uint32_t b0x = __shfl_sync(0xFFFFFFFFu, breg.x, j);
            uint32_t b0y = __shfl_sync(0xFFFFFFFFu, breg.y, j);
            uint32_t b1x = __shfl_sync(0xFFFFFFFFu, breg.x, j + 4);
            uint32_t b1y = __shfl_sync(0xFFFFFFFFu, breg.y, j + 4);
            uint32_t moff0 = ((uint32_t)(32 * t + 4 * q)) ^ mswz;
            uint32_t moff1 = moff0 ^ 16u;
            uint32_t mh00 = lds32(mh0b + moff0);
            uint32_t mh01 = lds32(mh0b + moff1);
            uint32_t mh10 = lds32(mh1b + moff0);
            uint32_t mh11 = lds32(mh1b + moff1);
            uint32_t ah0 = hmul2(hmax2(hmul2(Ah0, b0x), hmul2(A2h0, b0y)), mh00);
            uint32_t ah1 = hmul2(hmax2(hmul2(Ah1, b0x), hmul2(A2h1, b0y)), mh10);
            uint32_t ah2 = hmul2(hmax2(hmul2(Ah0, b1x), hmul2(A2h0, b1y)), mh01);
            uint32_t ah3 = hmul2(hmax2(hmul2(Ah1, b1x), hmul2(A2h1, b1y)), mh11);

            const uint32_t voff = ((uint32_t)(32 * t) + lm_koff) ^ vswz;
            uint32_t vA[4], vB[4], vC[4], vD[4];
#pragma unroll
            for (int pr = 0; pr < 4; pr++)
                LDSM4(vA[pr], vB[pr], vC[pr], vD[pr], sv + (pr * 16 + lm_row) * 128 + voff);
#pragma unroll
            for (int pr = 0; pr < 4; pr++) {
                MMAH(d[2 * pr],     ah0, ah1, ah2, ah3, vA[pr], vB[pr]);
                MMAH(d[2 * pr + 1], ah0, ah1, ah2, ah3, vC[pr], vD[pr]);
            }
            MMAH(drs, ah0, ah1, ah2, ah3, onesB, onesB);
        }
        breg = breg_next;
    }

    const float rv0 = __shfl_sync(0xFFFFFFFFu, drs[0], 0, 4);
    const float rv1 = __shfl_sync(0xFFFFFFFFu, drs[2], 0, 4);
    const float i0 = 1.0f / rv0;
    const float i1 = 1.0f / rv1;
    float* o0p = out + (size_t)(n0 + r0) * KFP + k * FPD + 2 * q;
    float* o1p = out + (size_t)(n0 + r1) * KFP + k * FPD + 2 * q;
#pragma unroll
    for (int nt = 0; nt < 8; nt++) {
        float z0 = d[nt][0] * i0, z1 = d[nt][1] * i0;
        float z2 = d[nt][2] * i1, z3 = d[nt][3] * i1;
        z0 = z0 > 0.f ? z0 : expm1f(z0); z0 = z0 > 0.f ? z0 : expm1f(z0);
        z1 = z1 > 0.f ? z1 : expm1f(z1); z1 = z1 > 0.f ? z1 : expm1f(z1);
        z2 = z2 > 0.f ? z2 : expm1f(z2); z2 = z2 > 0.f ? z2 : expm1f(z2);
        z3 = z3 > 0.f ? z3 : expm1f(z3); z3 = z3 > 0.f ? z3 : expm1f(z3);
        *(float2*)(o0p + nt * 8) = make_float2(z0, z1);
        *(float2*)(o1p + nt * 8) = make_float2(z2, z3);
    }

    if (mout) {
        const int cid = blockIdx.x;
        uint32_t base = CONV_UNITS + (uint32_t)cid * CTA_UNITS;
#pragma unroll 1
        for (int i = 0; i < (int)(CTA_UNITS / 256); i += 8) {
            uint2 v[8];
#pragma unroll
            for (int e = 0; e < 8; e++) {
                uint32_t u = base + (uint32_t)(i + e) * 256 + tid;
                v[e] = *(const uint2*)(g_maskh + (size_t)u * 4);
            }
#pragma unroll
            for (int e = 0; e < 8; e++) {
                uint32_t u = base + (uint32_t)(i + e) * 256 + tid;
                *(float4*)(mout + (size_t)u * 4) = m2f(v[e]);
            }
        }
    }
}

// ---------------- launch -----------------------------------------------------
extern "C" void kernel_launch(void* const* d_in, const int* in_sizes, int n_in,
                              void* d_out, int out_size) {
    const float* x  = (const float*)d_in[0];
    const float* W  = (const float*)d_in[1];
    const float* b  = (const float*)d_in[2];
    const float* al = (const float*)d_in[3];
    const float* ar = (const float*)d_in[4];
    const void*  m  = d_in[5];
    float* out = (float*)d_out;

    cudaFuncSetAttribute(gat_attn_mma, cudaFuncAttributeMaxDynamicSharedMemorySize, SMEM_ATTN);

    const int OUT_ELEMS  = NN * KFP;
    const int MASK_ELEMS = NN * NN;
    float* mout = (out_size >= OUT_ELEMS + MASK_ELEMS) ? (out + OUT_ELEMS) : nullptr;

    fused_gemm_canon<<<256 + CANON_BLKS, 256>>>(x, W, b, al, ar, m);
    gat_attn_mma<<<ATTN_GRID, 256, SMEM_ATTN>>>(out, mout);
}